// round 15
// baseline (speedup 1.0000x reference)
#include <cuda_runtime.h>
#include <cuda_bf16.h>
#include <cuda_fp16.h>
#include <math.h>
#include <stdint.h>

#define NB    4
#define S_LEN 4096
#define HID   2048
#define HD    128
#define NROWS (NB * S_LEN)          // 16384
#define LOG2E 1.4426950408889634f

// Split-KV chunking: chunk = 8 KV blocks.  nch(qb) = (qb>>3)+1.
#define CHUNK    8
#define N_TASKS  1152

// ---------------- scratch (no allocs allowed) ----------------
__device__ __nv_bfloat16 g_wthi[3 * HD * HID];   // [head][n][k] = W^T split hi
__device__ __nv_bfloat16 g_wtlo[3 * HD * HID];
__device__ __half g_qh[NROWS * HD];   // Q*log2e hi/lo fp16
__device__ __half g_ql[NROWS * HD];
__device__ __half g_kh[NROWS * HD];
__device__ __half g_kl[NROWS * HD];
__device__ __half g_vv[NROWS * HD];   // V fp16
__device__ __half g_po[N_TASKS][64][HD];  // unnormalized partial O (fp16)
__device__ float g_pml[N_TASKS][64][2];   // per-row {m, l}
__device__ int g_task;
__device__ int g_done[64 * NB];           // per-(qb,b) completed-chunk counters

// ======================= helpers =======================
__device__ __forceinline__ uint32_t smem_u32(const void* p) {
    uint32_t a;
    asm("{ .reg .u64 t; cvta.to.shared.u64 t, %1; cvt.u32.u64 %0, t; }" : "=r"(a) : "l"(p));
    return a;
}
__device__ __forceinline__ void cp16(uint32_t s, const void* g) {
    asm volatile("cp.async.cg.shared.global [%0], [%1], 16;" :: "r"(s), "l"(g));
}
__device__ __forceinline__ void cp_commit() {
    asm volatile("cp.async.commit_group;" ::: "memory");
}
__device__ __forceinline__ void cp_wait0() {
    asm volatile("cp.async.wait_group 0;" ::: "memory");
}
__device__ __forceinline__ void cp_wait1() {
    asm volatile("cp.async.wait_group 1;" ::: "memory");
}
__device__ __forceinline__ void cp_wait2() {
    asm volatile("cp.async.wait_group 2;" ::: "memory");
}
__device__ __forceinline__ void ldsm4(uint32_t* r, uint32_t addr) {
    asm volatile("ldmatrix.sync.aligned.m8n8.x4.shared.b16 {%0,%1,%2,%3}, [%4];"
                 : "=r"(r[0]), "=r"(r[1]), "=r"(r[2]), "=r"(r[3]) : "r"(addr));
}
__device__ __forceinline__ void ldsm4t(uint32_t* r, uint32_t addr) {
    asm volatile("ldmatrix.sync.aligned.m8n8.x4.trans.shared.b16 {%0,%1,%2,%3}, [%4];"
                 : "=r"(r[0]), "=r"(r[1]), "=r"(r[2]), "=r"(r[3]) : "r"(addr));
}
__device__ __forceinline__ void mma_bf16(float* d, const uint32_t* a, const uint32_t* b) {
    asm volatile(
        "mma.sync.aligned.m16n8k16.row.col.f32.bf16.bf16.f32 "
        "{%0,%1,%2,%3}, {%4,%5,%6,%7}, {%8,%9}, {%0,%1,%2,%3};"
        : "+f"(d[0]), "+f"(d[1]), "+f"(d[2]), "+f"(d[3])
        : "r"(a[0]), "r"(a[1]), "r"(a[2]), "r"(a[3]), "r"(b[0]), "r"(b[1]));
}
__device__ __forceinline__ void mma_f16(float* d, uint32_t a0, uint32_t a1, uint32_t a2,
                                        uint32_t a3, uint32_t b0, uint32_t b1) {
    asm volatile(
        "mma.sync.aligned.m16n8k16.row.col.f32.f16.f16.f32 "
        "{%0,%1,%2,%3}, {%4,%5,%6,%7}, {%8,%9}, {%0,%1,%2,%3};"
        : "+f"(d[0]), "+f"(d[1]), "+f"(d[2]), "+f"(d[3])
        : "r"(a0), "r"(a1), "r"(a2), "r"(a3), "r"(b0), "r"(b1));
}
__device__ __forceinline__ float ex2f(float x) {
    float r;
    asm("ex2.approx.f32 %0, %1;" : "=f"(r) : "f"(x));
    return r;
}
__device__ __forceinline__ uint32_t packh2(float lo, float hi) {
    uint32_t r;
    asm("cvt.rn.f16x2.f32 %0, %1, %2;" : "=r"(r) : "f"(hi), "f"(lo));
    return r;
}
__device__ __forceinline__ uint32_t h2ex2(uint32_t x) {
    uint32_t r;
    asm("ex2.approx.f16x2 %0, %1;" : "=r"(r) : "r"(x));
    return r;
}

// =====================================================================
// Kernel 0: transpose+split W via smem tiles (coalesced both sides).
// grid (2, 32, 3); 256 threads; 64x64 tiles.  Resets task + done ctrs.
// =====================================================================
__global__ void convert_w_kernel(const float* __restrict__ Wq,
                                 const float* __restrict__ Wk,
                                 const float* __restrict__ Wv)
{
    __shared__ float ts[64][65];
    const int t = threadIdx.x;
    if (blockIdx.x == 0 && blockIdx.y == 0 && blockIdx.z == 0) {
        if (t == 0) g_task = 0;
        if (t < 64 * NB) g_done[t] = 0;
    }

    const int head = blockIdx.z;
    const int k0 = blockIdx.y * 64;
    const int n0 = blockIdx.x * 64;
    const float* W = (head == 0) ? Wq : (head == 1) ? Wk : Wv;

    {
        const int r = t >> 4;
        const int c = (t & 15) * 4;
        #pragma unroll
        for (int i = 0; i < 4; ++i) {
            float4 v = *(const float4*)(W + (size_t)(k0 + r + i * 16) * HD + n0 + c);
            ts[r + i * 16][c]     = v.x;
            ts[r + i * 16][c + 1] = v.y;
            ts[r + i * 16][c + 2] = v.z;
            ts[r + i * 16][c + 3] = v.w;
        }
    }
    __syncthreads();

    {
        const int n   = t >> 2;
        const int ks0 = (t & 3) * 16;
        uint32_t hw[8], lw[8];
        #pragma unroll
        for (int j = 0; j < 8; ++j) {
            float v0 = ts[ks0 + 2 * j][n];
            float v1 = ts[ks0 + 2 * j + 1][n];
            __nv_bfloat16 h0 = __float2bfloat16(v0);
            __nv_bfloat16 h1 = __float2bfloat16(v1);
            __nv_bfloat16 l0 = __float2bfloat16(v0 - __bfloat162float(h0));
            __nv_bfloat16 l1 = __float2bfloat16(v1 - __bfloat162float(h1));
            __nv_bfloat162 hp = __halves2bfloat162(h0, h1);
            __nv_bfloat162 lp = __halves2bfloat162(l0, l1);
            hw[j] = *(uint32_t*)&hp;
            lw[j] = *(uint32_t*)&lp;
        }
        size_t base = (size_t)head * HD * HID + (size_t)(n0 + n) * HID + k0 + ks0;
        *(uint4*)(g_wthi + base)     = make_uint4(hw[0], hw[1], hw[2], hw[3]);
        *(uint4*)(g_wthi + base + 8) = make_uint4(hw[4], hw[5], hw[6], hw[7]);
        *(uint4*)(g_wtlo + base)     = make_uint4(lw[0], lw[1], lw[2], lw[3]);
        *(uint4*)(g_wtlo + base + 8) = make_uint4(lw[4], lw[5], lw[6], lw[7]);
    }
}

// =====================================================================
// Kernel 1: mma.sync bf16-split projection with FUSED x split.
// 512 threads (16 warps, 4x4, 32x32 warp tiles), 1 CTA/SM, grid(3,128).
// BK=64, 3-stage cp.async pipeline (round-13 champion version).
// =====================================================================
#define PJ_BK     64
#define PJ_NCHUNK (HID / PJ_BK)        // 32
#define PJ_LDS    72
#define PJ_TILE_B (128 * PJ_LDS * 2)
#define PJ_OF_AH  0
#define PJ_OF_AL  (PJ_TILE_B)
#define PJ_OF_BH  (2 * PJ_TILE_B)
#define PJ_OF_BL  (3 * PJ_TILE_B)
#define PJ_BUF_B  (4 * PJ_TILE_B)
#define PJ_SM_TOT (3 * PJ_BUF_B)        // 221184

__device__ __forceinline__ void split_store(__half* hi, __half* lo, size_t idx,
                                            float v0, float v1) {
    __half h0 = __float2half_rn(v0), h1 = __float2half_rn(v1);
    __half l0 = __float2half_rn(v0 - __half2float(h0));
    __half l1 = __float2half_rn(v1 - __half2float(h1));
    *(__half2*)(hi + idx) = __halves2half2(h0, h1);
    *(__half2*)(lo + idx) = __halves2half2(l0, l1);
}

__device__ __forceinline__ void split16(const float4* xv, uint32_t* hiw, uint32_t* low) {
    #pragma unroll
    for (int j = 0; j < 4; ++j) {
        float e[4] = {xv[j].x, xv[j].y, xv[j].z, xv[j].w};
        __nv_bfloat16 h[4], l[4];
        #pragma unroll
        for (int u = 0; u < 4; ++u) {
            h[u] = __float2bfloat16(e[u]);
            l[u] = __float2bfloat16(e[u] - __bfloat162float(h[u]));
        }
        __nv_bfloat162 hp0 = __halves2bfloat162(h[0], h[1]);
        __nv_bfloat162 hp1 = __halves2bfloat162(h[2], h[3]);
        __nv_bfloat162 lp0 = __halves2bfloat162(l[0], l[1]);
        __nv_bfloat162 lp1 = __halves2bfloat162(l[2], l[3]);
        hiw[2 * j]     = *(uint32_t*)&hp0;
        hiw[2 * j + 1] = *(uint32_t*)&hp1;
        low[2 * j]     = *(uint32_t*)&lp0;
        low[2 * j + 1] = *(uint32_t*)&lp1;
    }
}

__global__ __launch_bounds__(512, 1)
void proj_mma_kernel(const float* __restrict__ x,
                     const float* __restrict__ bq,
                     const float* __restrict__ bk,
                     const float* __restrict__ bv)
{
    extern __shared__ char smem[];
    const uint32_t sb = smem_u32(smem);

    const int t    = threadIdx.x;
    const int lane = t & 31;
    const int wid  = t >> 5;
    const int wm   = wid >> 2;
    const int wn   = wid & 3;
    const int head = blockIdx.x;
    const int m0   = blockIdx.y * 128;

    const __nv_bfloat16* wh = g_wthi + (size_t)head * HD * HID;
    const __nv_bfloat16* wl = g_wtlo + (size_t)head * HD * HID;

    const int lrow = t >> 2;
    const int lcs  = (t & 3) * 16;
    const float* xrow = x + (size_t)(m0 + lrow) * HID + lcs;
    const uint32_t a_so = (uint32_t)(lrow * PJ_LDS + lcs) * 2;
    const uint32_t b_so = (uint32_t)(lrow * PJ_LDS + lcs) * 2;
    const __nv_bfloat16* whrow = wh + (size_t)lrow * HID + lcs;
    const __nv_bfloat16* wlrow = wl + (size_t)lrow * HID + lcs;

    float acc[2][4][4];
    #pragma unroll
    for (int i = 0; i < 2; ++i)
        #pragma unroll
        for (int j = 0; j < 4; ++j)
            #pragma unroll
            for (int u = 0; u < 4; ++u) acc[i][j][u] = 0.f;

    {
        cp16(sb + PJ_OF_BH + b_so,      whrow);
        cp16(sb + PJ_OF_BH + b_so + 16, whrow + 8);
        cp16(sb + PJ_OF_BL + b_so,      wlrow);
        cp16(sb + PJ_OF_BL + b_so + 16, wlrow + 8);
        cp_commit();
        const uint32_t b1 = sb + PJ_BUF_B;
        cp16(b1 + PJ_OF_BH + b_so,      whrow + PJ_BK);
        cp16(b1 + PJ_OF_BH + b_so + 16, whrow + PJ_BK + 8);
        cp16(b1 + PJ_OF_BL + b_so,      wlrow + PJ_BK);
        cp16(b1 + PJ_OF_BL + b_so + 16, wlrow + PJ_BK + 8);
        cp_commit();
        float4 xv[4];
        #pragma unroll
        for (int j = 0; j < 4; ++j) xv[j] = ((const float4*)xrow)[j];
        uint32_t hiw[8], low[8];
        split16(xv, hiw, low);
        *(uint4*)(smem + PJ_OF_AH + a_so)      = make_uint4(hiw[0], hiw[1], hiw[2], hiw[3]);
        *(uint4*)(smem + PJ_OF_AH + a_so + 16) = make_uint4(hiw[4], hiw[5], hiw[6], hiw[7]);
        *(uint4*)(smem + PJ_OF_AL + a_so)      = make_uint4(low[0], low[1], low[2], low[3]);
        *(uint4*)(smem + PJ_OF_AL + a_so + 16) = make_uint4(low[4], low[5], low[6], low[7]);
    }

    int bufc = 0;
    for (int c = 0; c < PJ_NCHUNK; ++c) {
        if (c + 2 < PJ_NCHUNK) {
            const int kt = (c + 2) * PJ_BK;
            int bufn2 = bufc + 2; if (bufn2 >= 3) bufn2 -= 3;
            const uint32_t nb = sb + (uint32_t)bufn2 * PJ_BUF_B;
            cp16(nb + PJ_OF_BH + b_so,      whrow + kt);
            cp16(nb + PJ_OF_BH + b_so + 16, whrow + kt + 8);
            cp16(nb + PJ_OF_BL + b_so,      wlrow + kt);
            cp16(nb + PJ_OF_BL + b_so + 16, wlrow + kt + 8);
            cp_commit();
            cp_wait2();
        } else if (c + 1 < PJ_NCHUNK) {
            cp_wait1();
        } else {
            cp_wait0();
        }
        __syncthreads();

        float4 xv[4];
        const bool more = (c + 1 < PJ_NCHUNK);
        if (more) {
            const int kt = (c + 1) * PJ_BK;
            #pragma unroll
            for (int j = 0; j < 4; ++j) xv[j] = ((const float4*)(xrow + kt))[j];
        }

        const uint32_t bbase = sb + (uint32_t)bufc * PJ_BUF_B;
        const uint32_t sAh = bbase + PJ_OF_AH;
        const uint32_t sAl = bbase + PJ_OF_AL;
        const uint32_t sBh = bbase + PJ_OF_BH;
        const uint32_t sBl = bbase + PJ_OF_BL;

        #pragma unroll
        for (int ks = 0; ks < 4; ++ks) {
            uint32_t bh[4][2], bl[4][2];
            #pragma unroll
            for (int g = 0; g < 2; ++g) {
                uint32_t off = (uint32_t)((wn * 32 + g * 16 + (lane & 15)) * PJ_LDS
                                          + ks * 16 + (lane >> 4) * 8) * 2;
                uint32_t r[4];
                ldsm4(r, sBh + off);
                bh[2 * g][0] = r[0]; bh[2 * g + 1][0] = r[1];
                bh[2 * g][1] = r[2]; bh[2 * g + 1][1] = r[3];
                ldsm4(r, sBl + off);
                bl[2 * g][0] = r[0]; bl[2 * g + 1][0] = r[1];
                bl[2 * g][1] = r[2]; bl[2 * g + 1][1] = r[3];
            }
            uint32_t ah[2][4], al[2][4];
            #pragma unroll
            for (int mt = 0; mt < 2; ++mt) {
                uint32_t off = (uint32_t)((wm * 32 + mt * 16 + (lane & 15)) * PJ_LDS
                                          + ks * 16 + (lane >> 4) * 8) * 2;
                ldsm4(ah[mt], sAh + off);
                ldsm4(al[mt], sAl + off);
            }
            #pragma unroll
            for (int mt = 0; mt < 2; ++mt)
                #pragma unroll
                for (int nt = 0; nt < 4; ++nt)
                    mma_bf16(acc[mt][nt], ah[mt], bh[nt]);
            #pragma unroll
            for (int mt = 0; mt < 2; ++mt)
                #pragma unroll
                for (int nt = 0; nt < 4; ++nt)
                    mma_bf16(acc[mt][nt], ah[mt], bl[nt]);
            #pragma unroll
            for (int mt = 0; mt < 2; ++mt)
                #pragma unroll
                for (int nt = 0; nt < 4; ++nt)
                    mma_bf16(acc[mt][nt], al[mt], bh[nt]);
        }

        if (more) {
            int bufn = bufc + 1; if (bufn >= 3) bufn -= 3;
            uint32_t hiw[8], low[8];
            split16(xv, hiw, low);
            char* nbp = smem + (size_t)bufn * PJ_BUF_B;
            *(uint4*)(nbp + PJ_OF_AH + a_so)      = make_uint4(hiw[0], hiw[1], hiw[2], hiw[3]);
            *(uint4*)(nbp + PJ_OF_AH + a_so + 16) = make_uint4(hiw[4], hiw[5], hiw[6], hiw[7]);
            *(uint4*)(nbp + PJ_OF_AL + a_so)      = make_uint4(low[0], low[1], low[2], low[3]);
            *(uint4*)(nbp + PJ_OF_AL + a_so + 16) = make_uint4(low[4], low[5], low[6], low[7]);
        }
        if (++bufc >= 3) bufc = 0;
    }

    // epilogue: bias (+log2e scale for Q) + fp16 split/plain store
    const float* bias = (head == 0) ? bq : (head == 1) ? bk : bv;
    const float scl = (head == 0) ? LOG2E : 1.0f;
    const int qrow = lane >> 2;
    const int qcol = (lane & 3) * 2;
    #pragma unroll
    for (int mt = 0; mt < 2; ++mt) {
        int row0 = m0 + wm * 32 + mt * 16 + qrow;
        #pragma unroll
        for (int nt = 0; nt < 4; ++nt) {
            int col = wn * 32 + nt * 8 + qcol;
            float b0 = __ldg(bias + col), b1 = __ldg(bias + col + 1);
            float v0 = (acc[mt][nt][0] + b0) * scl;
            float v1 = (acc[mt][nt][1] + b1) * scl;
            float v2 = (acc[mt][nt][2] + b0) * scl;
            float v3 = (acc[mt][nt][3] + b1) * scl;
            size_t i0 = (size_t)row0 * HD + col;
            size_t i1 = (size_t)(row0 + 8) * HD + col;
            if (head == 0) {
                split_store(g_qh, g_ql, i0, v0, v1);
                split_store(g_qh, g_ql, i1, v2, v3);
            } else if (head == 1) {
                split_store(g_kh, g_kl, i0, v0, v1);
                split_store(g_kh, g_kl, i1, v2, v3);
            } else {
                *(uint32_t*)(g_vv + i0) = packh2(v0, v1);
                *(uint32_t*)(g_vv + i1) = packh2(v2, v3);
            }
        }
    }
}

// =====================================================================
// Kernel 2: fp16 tensor-core causal flash attention, SPLIT-KV, with
// INLINE last-finisher merge (no separate merge kernel).
// =====================================================================
#define QSTRB 272
#define VSTRB 304
#define ST_B  54272
#define ST_KH 0
#define ST_KL 17408
#define ST_V  34816
#define SM_TASK 108544
#define SM_FIN  108548
#define SM_ATT_TOT 108560

__global__ __launch_bounds__(128)
void attn_kernel(float* __restrict__ outp)
{
    extern __shared__ char smem[];
    const uint32_t sb = smem_u32(smem);
    const int t = threadIdx.x;
    const int l = t & 31;
    const int w = t >> 5;

    const float cf = 0.0883883476483184406f;   // 1/sqrt(128)

    const uint32_t qa_off = (uint32_t)(w * 16 + (l & 15)) * QSTRB + ((l >> 4) * 8) * 2;
    const uint32_t kb_row = (uint32_t)((l >> 4) * 8 + (l & 7)) * QSTRB;
    const uint32_t kb_col = (uint32_t)(((l >> 3) & 1) * 8) * 2;
    const uint32_t vb_row = (uint32_t)(((l >> 3) & 1) * 8 + (l & 7)) * VSTRB;
    const uint32_t vb_col = (uint32_t)((l >> 4) * 8) * 2;

    while (true) {
        __syncthreads();
        // re-init V pad columns each task (merge may have clobbered smem)
        #pragma unroll
        for (int s2 = 0; s2 < 2; ++s2)
            for (int i = t; i < 64 * 16; i += 128) {
                int row = i >> 4;
                int c   = 128 + (i & 15);
                ((__half*)(smem + s2 * ST_B + ST_V))[row * 152 + c] =
                    (c == 128) ? __float2half(1.0f) : __float2half(0.0f);
            }
        if (t == 0) *(int*)(smem + SM_TASK) = atomicAdd(&g_task, 1);
        __syncthreads();
        const int task = *(int*)(smem + SM_TASK);
        if (task >= N_TASKS) break;

        int id = task, qb = 63, ch, b;
        for (;;) {
            int cnt = 4 * ((qb >> 3) + 1);
            if (id < cnt) { ch = id >> 2; b = id & 3; break; }
            id -= cnt; --qb;
        }
        const int base = task - (ch * 4 + b);   // first slot of this qb
        const int nch  = (qb >> 3) + 1;
        const int q0  = qb * 64;
        const int kv0 = ch * CHUNK;
        const int kv1 = min(kv0 + CHUNK, qb + 1);

        const __half* qh = g_qh + (size_t)b * S_LEN * HD;
        const __half* ql = g_ql + (size_t)b * S_LEN * HD;
        const __half* kh = g_kh + (size_t)b * S_LEN * HD;
        const __half* kl = g_kl + (size_t)b * S_LEN * HD;
        const __half* vv = g_vv + (size_t)b * S_LEN * HD;

        #pragma unroll
        for (int p = 0; p < 8; ++p) {
            int vec = t + 128 * p;
            int row = vec >> 4;
            int cv  = vec & 15;
            uint32_t so = (uint32_t)row * QSTRB + cv * 16;
            const size_t g = (size_t)(q0 + row) * HD + cv * 8;
            cp16(sb + ST_KH + so, qh + g);
            cp16(sb + ST_KL + so, ql + g);
        }
        cp_commit();
        cp_wait0();
        __syncthreads();

        uint32_t qah[8][4], qal[8][4];
        #pragma unroll
        for (int ks = 0; ks < 8; ++ks) {
            ldsm4(qah[ks], sb + ST_KH + qa_off + ks * 32);
            ldsm4(qal[ks], sb + ST_KL + qa_off + ks * 32);
        }
        __syncthreads();

        #pragma unroll
        for (int p = 0; p < 8; ++p) {
            int vec = t + 128 * p;
            int row = vec >> 4;
            int cv  = vec & 15;
            const size_t g = (size_t)(kv0 * 64 + row) * HD + cv * 8;
            cp16(sb + (uint32_t)(kv0 & 1) * ST_B + ST_KH + (uint32_t)row * QSTRB + cv * 16, kh + g);
            cp16(sb + (uint32_t)(kv0 & 1) * ST_B + ST_KL + (uint32_t)row * QSTRB + cv * 16, kl + g);
            cp16(sb + (uint32_t)(kv0 & 1) * ST_B + ST_V  + (uint32_t)row * VSTRB + cv * 16, vv + g);
        }
        cp_commit();

        float o[18][4];
        #pragma unroll
        for (int i = 0; i < 18; ++i)
            #pragma unroll
            for (int u = 0; u < 4; ++u) o[i][u] = 0.f;
        float mA = -1e4f, mB = -1e4f;

        const int rA = w * 16 + (l >> 2);
        const int rB = rA + 8;

        for (int kb = kv0; kb < kv1; ++kb) {
            cp_wait0();
            __syncthreads();

            const uint32_t cb = sb + (uint32_t)(kb & 1) * ST_B;

            float s[8][4];
            #pragma unroll
            for (int n = 0; n < 8; ++n)
                #pragma unroll
                for (int u = 0; u < 4; ++u) s[n][u] = 0.f;

            #pragma unroll
            for (int ks = 0; ks < 8; ++ks) {
                uint32_t bh[4][4], bl[4][4];
                #pragma unroll
                for (int u = 0; u < 4; ++u) {
                    uint32_t off = (uint32_t)(u * 16) * QSTRB + kb_row + ks * 32 + kb_col;
                    ldsm4(bh[u], cb + ST_KH + off);
                    ldsm4(bl[u], cb + ST_KL + off);
                }
                #pragma unroll
                for (int u = 0; u < 4; ++u) {
                    mma_f16(s[2 * u],     qah[ks][0], qah[ks][1], qah[ks][2], qah[ks][3], bh[u][0], bh[u][1]);
                    mma_f16(s[2 * u + 1], qah[ks][0], qah[ks][1], qah[ks][2], qah[ks][3], bh[u][2], bh[u][3]);
                }
                #pragma unroll
                for (int u = 0; u < 4; ++u) {
                    mma_f16(s[2 * u],     qah[ks][0], qah[ks][1], qah[ks][2], qah[ks][3], bl[u][0], bl[u][1]);
                    mma_f16(s[2 * u + 1], qah[ks][0], qah[ks][1], qah[ks][2], qah[ks][3], bl[u][2], bl[u][3]);
                }
                #pragma unroll
                for (int u = 0; u < 4; ++u) {
                    mma_f16(s[2 * u],     qal[ks][0], qal[ks][1], qal[ks][2], qal[ks][3], bh[u][0], bh[u][1]);
                    mma_f16(s[2 * u + 1], qal[ks][0], qal[ks][1], qal[ks][2], qal[ks][3], bh[u][2], bh[u][3]);
                }
            }

            if (kb + 1 < kv1) {
                const uint32_t nb = sb + (uint32_t)((kb + 1) & 1) * ST_B;
                #pragma unroll
                for (int p = 0; p < 8; ++p) {
                    int vec = t + 128 * p;
                    int row = vec >> 4;
                    int cv  = vec & 15;
                    const size_t g = (size_t)((kb + 1) * 64 + row) * HD + cv * 8;
                    cp16(nb + ST_KH + (uint32_t)row * QSTRB + cv * 16, kh + g);
                    cp16(nb + ST_KL + (uint32_t)row * QSTRB + cv * 16, kl + g);
                    cp16(nb + ST_V  + (uint32_t)row * VSTRB + cv * 16, vv + g);
                }
                cp_commit();
            }

            if (kb == qb) {
                #pragma unroll
                for (int n = 0; n < 8; ++n) {
                    int c0 = n * 8 + 2 * (l & 3);
                    if (c0     > rA) s[n][0] = -1e30f;
                    if (c0 + 1 > rA) s[n][1] = -1e30f;
                    if (c0     > rB) s[n][2] = -1e30f;
                    if (c0 + 1 > rB) s[n][3] = -1e30f;
                }
            }

            float mxA = s[0][0], mxB = s[0][2];
            #pragma unroll
            for (int n = 0; n < 8; ++n) {
                mxA = fmaxf(mxA, fmaxf(s[n][0], s[n][1]));
                mxB = fmaxf(mxB, fmaxf(s[n][2], s[n][3]));
            }
            mxA = fmaxf(mxA, __shfl_xor_sync(0xffffffffu, mxA, 1));
            mxA = fmaxf(mxA, __shfl_xor_sync(0xffffffffu, mxA, 2));
            mxB = fmaxf(mxB, __shfl_xor_sync(0xffffffffu, mxB, 1));
            mxB = fmaxf(mxB, __shfl_xor_sync(0xffffffffu, mxB, 2));
            const float nmA = fmaxf(mA, mxA);
            const float nmB = fmaxf(mB, mxB);

            uint32_t pA[8], pB[8];
            #pragma unroll
            for (int n = 0; n < 8; ++n) {
                pA[n] = h2ex2(packh2(s[n][0] - nmA, s[n][1] - nmA));
                pB[n] = h2ex2(packh2(s[n][2] - nmB, s[n][3] - nmB));
            }

            if (nmA > mA) {
                float aA = ex2f(mA - nmA);
                #pragma unroll
                for (int i = 0; i < 17; ++i) { o[i][0] *= aA; o[i][1] *= aA; }
                mA = nmA;
            }
            if (nmB > mB) {
                float aB = ex2f(mB - nmB);
                #pragma unroll
                for (int i = 0; i < 17; ++i) { o[i][2] *= aB; o[i][3] *= aB; }
                mB = nmB;
            }

            #pragma unroll
            for (int kt = 0; kt < 4; ++kt) {
                uint32_t a0 = pA[2 * kt], a1 = pB[2 * kt];
                uint32_t a2 = pA[2 * kt + 1], a3 = pB[2 * kt + 1];
                uint32_t vb[9][4];
                #pragma unroll
                for (int u = 0; u < 9; ++u) {
                    uint32_t off = (uint32_t)(kt * 16) * VSTRB + vb_row + u * 32 + vb_col;
                    ldsm4t(vb[u], cb + ST_V + off);
                }
                #pragma unroll
                for (int u = 0; u < 9; ++u) {
                    mma_f16(o[2 * u],     a0, a1, a2, a3, vb[u][0], vb[u][1]);
                    mma_f16(o[2 * u + 1], a0, a1, a2, a3, vb[u][2], vb[u][3]);
                }
            }
            __syncthreads();
        }

        // ---- epilogue: write fp16 unnormalized partial + fp32 stats ----
        __half (*po)[HD] = g_po[task];
        #pragma unroll
        for (int n = 0; n < 16; ++n) {
            int c = n * 8 + 2 * (l & 3);
            *(uint32_t*)(&po[rA][c]) = packh2(o[n][0], o[n][1]);
            *(uint32_t*)(&po[rB][c]) = packh2(o[n][2], o[n][3]);
        }
        if ((l & 3) == 0) {
            g_pml[task][rA][0] = mA;
            g_pml[task][rA][1] = o[16][0];
            g_pml[task][rB][0] = mB;
            g_pml[task][rB][1] = o[16][2];
        }

        // ---- last-finisher merge for (qb, b) ----
        __threadfence();     // release partials before counter bump
        __syncthreads();     // all threads' stores done before t0's fence+atomic
        if (t == 0) {
            int old = atomicAdd(&g_done[qb * NB + b], 1);
            *(int*)(smem + SM_FIN) = (old == nch - 1) ? 1 : 0;
        }
        __syncthreads();
        if (*(int*)(smem + SM_FIN)) {
            __threadfence();   // acquire: other finishers' partials now visible
            float* wsh = (float*)smem;            // [8][64] weights
            float* ssc = (float*)(smem + 2048);   // [64] scales
            if (t < 64) {
                float m2[8], lv[8];
                float M = -1e30f;
                for (int i = 0; i < nch; ++i) {
                    int slot = base + 4 * i + b;
                    m2[i] = g_pml[slot][t][0];
                    lv[i] = g_pml[slot][t][1];
                    M = fmaxf(M, m2[i]);
                }
                float L = 0.f;
                for (int i = 0; i < nch; ++i) {
                    float wi = ex2f(m2[i] - M);
                    wsh[i * 64 + t] = wi;
                    L += wi * lv[i];
                }
                ssc[t] = cf / L;
            }
            __syncthreads();
            float* op = outp + ((size_t)b * S_LEN + (size_t)qb * 64) * HD;
            for (int e = t; e < 64 * 64; e += 128) {
                int r  = e >> 6;
                int h2 = e & 63;
                float ax = 0.f, ay = 0.f;
                for (int i = 0; i < nch; ++i) {
                    int slot = base + 4 * i + b;
                    __half2 v = ((const __half2*)g_po[slot][r])[h2];
                    float2 f = __half22float2(v);
                    ax += wsh[i * 64 + r] * f.x;
                    ay += wsh[i * 64 + r] * f.y;
                }
                float2 res;
                res.x = ax * ssc[r];
                res.y = ay * ssc[r];
                *(float2*)(op + (size_t)r * HD + 2 * h2) = res;
            }
        }
    }
}

// =====================================================================
extern "C" void kernel_launch(void* const* d_in, const int* in_sizes, int n_in,
                              void* d_out, int out_size)
{
    const float* x  = (const float*)d_in[0];
    const float* Wq = (const float*)d_in[1];
    const float* bq = (const float*)d_in[2];
    const float* Wk = (const float*)d_in[3];
    const float* bk = (const float*)d_in[4];
    const float* Wv = (const float*)d_in[5];
    const float* bv = (const float*)d_in[6];
    float* out = (float*)d_out;

    dim3 cwg(2, 32, 3);
    convert_w_kernel<<<cwg, 256>>>(Wq, Wk, Wv);

    cudaFuncSetAttribute(proj_mma_kernel,
                         cudaFuncAttributeMaxDynamicSharedMemorySize, PJ_SM_TOT);
    dim3 pg(3, 128);
    proj_mma_kernel<<<pg, 512, PJ_SM_TOT>>>(x, bq, bk, bv);

    cudaFuncSetAttribute(attn_kernel,
                         cudaFuncAttributeMaxDynamicSharedMemorySize, SM_ATT_TOT);
    attn_kernel<<<296, 128, SM_ATT_TOT>>>(out);
}

// round 16
// speedup vs baseline: 1.0360x; 1.0360x over previous
#include <cuda_runtime.h>
#include <cuda_bf16.h>
#include <cuda_fp16.h>
#include <math.h>
#include <stdint.h>

#define NB    4
#define S_LEN 4096
#define HID   2048
#define HD    128
#define NROWS (NB * S_LEN)          // 16384
#define LOG2E 1.4426950408889634f

// Split-KV chunking: chunk = 8 KV blocks.  nch(qb) = (qb>>3)+1.
#define CHUNK    8
#define N_TASKS  1152

// ---------------- scratch (no allocs allowed) ----------------
__device__ __nv_bfloat16 g_wthi[3 * HD * HID];   // [head][n][k] = W^T split hi
__device__ __nv_bfloat16 g_wtlo[3 * HD * HID];
__device__ __half g_qh[NROWS * HD];   // Q*log2e hi/lo fp16
__device__ __half g_ql[NROWS * HD];
__device__ __half g_kh[NROWS * HD];
__device__ __half g_kl[NROWS * HD];
__device__ __half g_vv[NROWS * HD];   // V fp16
__device__ __half g_po[N_TASKS][64][HD];  // unnormalized partial O (fp16)
__device__ float g_pml[N_TASKS][64][2];   // per-row {m, l}
__device__ int g_task;

// ======================= helpers =======================
__device__ __forceinline__ uint32_t smem_u32(const void* p) {
    uint32_t a;
    asm("{ .reg .u64 t; cvta.to.shared.u64 t, %1; cvt.u32.u64 %0, t; }" : "=r"(a) : "l"(p));
    return a;
}
__device__ __forceinline__ void cp16(uint32_t s, const void* g) {
    asm volatile("cp.async.cg.shared.global [%0], [%1], 16;" :: "r"(s), "l"(g));
}
__device__ __forceinline__ void cp_commit() {
    asm volatile("cp.async.commit_group;" ::: "memory");
}
__device__ __forceinline__ void cp_wait0() {
    asm volatile("cp.async.wait_group 0;" ::: "memory");
}
__device__ __forceinline__ void cp_wait1() {
    asm volatile("cp.async.wait_group 1;" ::: "memory");
}
__device__ __forceinline__ void cp_wait2() {
    asm volatile("cp.async.wait_group 2;" ::: "memory");
}
__device__ __forceinline__ void ldsm4(uint32_t* r, uint32_t addr) {
    asm volatile("ldmatrix.sync.aligned.m8n8.x4.shared.b16 {%0,%1,%2,%3}, [%4];"
                 : "=r"(r[0]), "=r"(r[1]), "=r"(r[2]), "=r"(r[3]) : "r"(addr));
}
__device__ __forceinline__ void ldsm4t(uint32_t* r, uint32_t addr) {
    asm volatile("ldmatrix.sync.aligned.m8n8.x4.trans.shared.b16 {%0,%1,%2,%3}, [%4];"
                 : "=r"(r[0]), "=r"(r[1]), "=r"(r[2]), "=r"(r[3]) : "r"(addr));
}
__device__ __forceinline__ void mma_bf16(float* d, const uint32_t* a, const uint32_t* b) {
    asm volatile(
        "mma.sync.aligned.m16n8k16.row.col.f32.bf16.bf16.f32 "
        "{%0,%1,%2,%3}, {%4,%5,%6,%7}, {%8,%9}, {%0,%1,%2,%3};"
        : "+f"(d[0]), "+f"(d[1]), "+f"(d[2]), "+f"(d[3])
        : "r"(a[0]), "r"(a[1]), "r"(a[2]), "r"(a[3]), "r"(b[0]), "r"(b[1]));
}
__device__ __forceinline__ void mma_f16(float* d, uint32_t a0, uint32_t a1, uint32_t a2,
                                        uint32_t a3, uint32_t b0, uint32_t b1) {
    asm volatile(
        "mma.sync.aligned.m16n8k16.row.col.f32.f16.f16.f32 "
        "{%0,%1,%2,%3}, {%4,%5,%6,%7}, {%8,%9}, {%0,%1,%2,%3};"
        : "+f"(d[0]), "+f"(d[1]), "+f"(d[2]), "+f"(d[3])
        : "r"(a0), "r"(a1), "r"(a2), "r"(a3), "r"(b0), "r"(b1));
}
__device__ __forceinline__ float ex2f(float x) {
    float r;
    asm("ex2.approx.f32 %0, %1;" : "=f"(r) : "f"(x));
    return r;
}
__device__ __forceinline__ uint32_t packh2(float lo, float hi) {
    uint32_t r;
    asm("cvt.rn.f16x2.f32 %0, %1, %2;" : "=r"(r) : "f"(hi), "f"(lo));
    return r;
}
__device__ __forceinline__ uint32_t h2ex2(uint32_t x) {
    uint32_t r;
    asm("ex2.approx.f16x2 %0, %1;" : "=r"(r) : "r"(x));
    return r;
}

// =====================================================================
// Kernel 0: transpose+split W via smem tiles (coalesced both sides).
// grid (2, 32, 3) = (n-tile, k-tile, head); 256 threads; 64x64 tiles.
// Also resets the persistent-attention task counter.
// =====================================================================
__global__ void convert_w_kernel(const float* __restrict__ Wq,
                                 const float* __restrict__ Wk,
                                 const float* __restrict__ Wv)
{
    __shared__ float ts[64][65];
    const int t = threadIdx.x;
    if (blockIdx.x == 0 && blockIdx.y == 0 && blockIdx.z == 0 && t == 0) g_task = 0;

    const int head = blockIdx.z;
    const int k0 = blockIdx.y * 64;
    const int n0 = blockIdx.x * 64;
    const float* W = (head == 0) ? Wq : (head == 1) ? Wk : Wv;

    // coalesced load: 64x64 fp32 tile
    {
        const int r = t >> 4;            // 0..15
        const int c = (t & 15) * 4;      // 0..60
        #pragma unroll
        for (int i = 0; i < 4; ++i) {
            float4 v = *(const float4*)(W + (size_t)(k0 + r + i * 16) * HD + n0 + c);
            ts[r + i * 16][c]     = v.x;
            ts[r + i * 16][c + 1] = v.y;
            ts[r + i * 16][c + 2] = v.z;
            ts[r + i * 16][c + 3] = v.w;
        }
    }
    __syncthreads();

    // transposed, split, coalesced store: each thread owns (n, 16 k's)
    {
        const int n   = t >> 2;          // 0..63
        const int ks0 = (t & 3) * 16;    // 0,16,32,48
        uint32_t hw[8], lw[8];
        #pragma unroll
        for (int j = 0; j < 8; ++j) {
            float v0 = ts[ks0 + 2 * j][n];
            float v1 = ts[ks0 + 2 * j + 1][n];
            __nv_bfloat16 h0 = __float2bfloat16(v0);
            __nv_bfloat16 h1 = __float2bfloat16(v1);
            __nv_bfloat16 l0 = __float2bfloat16(v0 - __bfloat162float(h0));
            __nv_bfloat16 l1 = __float2bfloat16(v1 - __bfloat162float(h1));
            __nv_bfloat162 hp = __halves2bfloat162(h0, h1);
            __nv_bfloat162 lp = __halves2bfloat162(l0, l1);
            hw[j] = *(uint32_t*)&hp;
            lw[j] = *(uint32_t*)&lp;
        }
        size_t base = (size_t)head * HD * HID + (size_t)(n0 + n) * HID + k0 + ks0;
        *(uint4*)(g_wthi + base)     = make_uint4(hw[0], hw[1], hw[2], hw[3]);
        *(uint4*)(g_wthi + base + 8) = make_uint4(hw[4], hw[5], hw[6], hw[7]);
        *(uint4*)(g_wtlo + base)     = make_uint4(lw[0], lw[1], lw[2], lw[3]);
        *(uint4*)(g_wtlo + base + 8) = make_uint4(lw[4], lw[5], lw[6], lw[7]);
    }
}

// =====================================================================
// Kernel 1: mma.sync bf16-split projection with FUSED x split.
// 512 threads (16 warps, 4x4, 32x32 warp tiles), 1 CTA/SM, grid(3,128).
// BK=64, 3-stage cp.async pipeline (round-13 champion version).
// =====================================================================
#define PJ_BK     64
#define PJ_NCHUNK (HID / PJ_BK)        // 32
#define PJ_LDS    72
#define PJ_TILE_B (128 * PJ_LDS * 2)
#define PJ_OF_AH  0
#define PJ_OF_AL  (PJ_TILE_B)
#define PJ_OF_BH  (2 * PJ_TILE_B)
#define PJ_OF_BL  (3 * PJ_TILE_B)
#define PJ_BUF_B  (4 * PJ_TILE_B)
#define PJ_SM_TOT (3 * PJ_BUF_B)        // 221184

__device__ __forceinline__ void split_store(__half* hi, __half* lo, size_t idx,
                                            float v0, float v1) {
    __half h0 = __float2half_rn(v0), h1 = __float2half_rn(v1);
    __half l0 = __float2half_rn(v0 - __half2float(h0));
    __half l1 = __float2half_rn(v1 - __half2float(h1));
    *(__half2*)(hi + idx) = __halves2half2(h0, h1);
    *(__half2*)(lo + idx) = __halves2half2(l0, l1);
}

// convert 16 fp32 (4 float4) -> 8+8 packed bf16x2 words (hi, lo)
__device__ __forceinline__ void split16(const float4* xv, uint32_t* hiw, uint32_t* low) {
    #pragma unroll
    for (int j = 0; j < 4; ++j) {
        float e[4] = {xv[j].x, xv[j].y, xv[j].z, xv[j].w};
        __nv_bfloat16 h[4], l[4];
        #pragma unroll
        for (int u = 0; u < 4; ++u) {
            h[u] = __float2bfloat16(e[u]);
            l[u] = __float2bfloat16(e[u] - __bfloat162float(h[u]));
        }
        __nv_bfloat162 hp0 = __halves2bfloat162(h[0], h[1]);
        __nv_bfloat162 hp1 = __halves2bfloat162(h[2], h[3]);
        __nv_bfloat162 lp0 = __halves2bfloat162(l[0], l[1]);
        __nv_bfloat162 lp1 = __halves2bfloat162(l[2], l[3]);
        hiw[2 * j]     = *(uint32_t*)&hp0;
        hiw[2 * j + 1] = *(uint32_t*)&hp1;
        low[2 * j]     = *(uint32_t*)&lp0;
        low[2 * j + 1] = *(uint32_t*)&lp1;
    }
}

__global__ __launch_bounds__(512, 1)
void proj_mma_kernel(const float* __restrict__ x,
                     const float* __restrict__ bq,
                     const float* __restrict__ bk,
                     const float* __restrict__ bv)
{
    extern __shared__ char smem[];
    const uint32_t sb = smem_u32(smem);

    const int t    = threadIdx.x;
    const int lane = t & 31;
    const int wid  = t >> 5;
    const int wm   = wid >> 2;
    const int wn   = wid & 3;
    const int head = blockIdx.x;
    const int m0   = blockIdx.y * 128;

    const __nv_bfloat16* wh = g_wthi + (size_t)head * HD * HID;
    const __nv_bfloat16* wl = g_wtlo + (size_t)head * HD * HID;

    const int lrow = t >> 2;
    const int lcs  = (t & 3) * 16;
    const float* xrow = x + (size_t)(m0 + lrow) * HID + lcs;
    const uint32_t a_so = (uint32_t)(lrow * PJ_LDS + lcs) * 2;
    const uint32_t b_so = (uint32_t)(lrow * PJ_LDS + lcs) * 2;
    const __nv_bfloat16* whrow = wh + (size_t)lrow * HID + lcs;
    const __nv_bfloat16* wlrow = wl + (size_t)lrow * HID + lcs;

    float acc[2][4][4];
    #pragma unroll
    for (int i = 0; i < 2; ++i)
        #pragma unroll
        for (int j = 0; j < 4; ++j)
            #pragma unroll
            for (int u = 0; u < 4; ++u) acc[i][j][u] = 0.f;

    {
        cp16(sb + PJ_OF_BH + b_so,      whrow);
        cp16(sb + PJ_OF_BH + b_so + 16, whrow + 8);
        cp16(sb + PJ_OF_BL + b_so,      wlrow);
        cp16(sb + PJ_OF_BL + b_so + 16, wlrow + 8);
        cp_commit();
        const uint32_t b1 = sb + PJ_BUF_B;
        cp16(b1 + PJ_OF_BH + b_so,      whrow + PJ_BK);
        cp16(b1 + PJ_OF_BH + b_so + 16, whrow + PJ_BK + 8);
        cp16(b1 + PJ_OF_BL + b_so,      wlrow + PJ_BK);
        cp16(b1 + PJ_OF_BL + b_so + 16, wlrow + PJ_BK + 8);
        cp_commit();
        float4 xv[4];
        #pragma unroll
        for (int j = 0; j < 4; ++j) xv[j] = ((const float4*)xrow)[j];
        uint32_t hiw[8], low[8];
        split16(xv, hiw, low);
        *(uint4*)(smem + PJ_OF_AH + a_so)      = make_uint4(hiw[0], hiw[1], hiw[2], hiw[3]);
        *(uint4*)(smem + PJ_OF_AH + a_so + 16) = make_uint4(hiw[4], hiw[5], hiw[6], hiw[7]);
        *(uint4*)(smem + PJ_OF_AL + a_so)      = make_uint4(low[0], low[1], low[2], low[3]);
        *(uint4*)(smem + PJ_OF_AL + a_so + 16) = make_uint4(low[4], low[5], low[6], low[7]);
    }

    int bufc = 0;
    for (int c = 0; c < PJ_NCHUNK; ++c) {
        if (c + 2 < PJ_NCHUNK) {
            const int kt = (c + 2) * PJ_BK;
            int bufn2 = bufc + 2; if (bufn2 >= 3) bufn2 -= 3;
            const uint32_t nb = sb + (uint32_t)bufn2 * PJ_BUF_B;
            cp16(nb + PJ_OF_BH + b_so,      whrow + kt);
            cp16(nb + PJ_OF_BH + b_so + 16, whrow + kt + 8);
            cp16(nb + PJ_OF_BL + b_so,      wlrow + kt);
            cp16(nb + PJ_OF_BL + b_so + 16, wlrow + kt + 8);
            cp_commit();
            cp_wait2();
        } else if (c + 1 < PJ_NCHUNK) {
            cp_wait1();
        } else {
            cp_wait0();
        }
        __syncthreads();

        float4 xv[4];
        const bool more = (c + 1 < PJ_NCHUNK);
        if (more) {
            const int kt = (c + 1) * PJ_BK;
            #pragma unroll
            for (int j = 0; j < 4; ++j) xv[j] = ((const float4*)(xrow + kt))[j];
        }

        const uint32_t bbase = sb + (uint32_t)bufc * PJ_BUF_B;
        const uint32_t sAh = bbase + PJ_OF_AH;
        const uint32_t sAl = bbase + PJ_OF_AL;
        const uint32_t sBh = bbase + PJ_OF_BH;
        const uint32_t sBl = bbase + PJ_OF_BL;

        #pragma unroll
        for (int ks = 0; ks < 4; ++ks) {
            uint32_t bh[4][2], bl[4][2];
            #pragma unroll
            for (int g = 0; g < 2; ++g) {
                uint32_t off = (uint32_t)((wn * 32 + g * 16 + (lane & 15)) * PJ_LDS
                                          + ks * 16 + (lane >> 4) * 8) * 2;
                uint32_t r[4];
                ldsm4(r, sBh + off);
                bh[2 * g][0] = r[0]; bh[2 * g + 1][0] = r[1];
                bh[2 * g][1] = r[2]; bh[2 * g + 1][1] = r[3];
                ldsm4(r, sBl + off);
                bl[2 * g][0] = r[0]; bl[2 * g + 1][0] = r[1];
                bl[2 * g][1] = r[2]; bl[2 * g + 1][1] = r[3];
            }
            uint32_t ah[2][4], al[2][4];
            #pragma unroll
            for (int mt = 0; mt < 2; ++mt) {
                uint32_t off = (uint32_t)((wm * 32 + mt * 16 + (lane & 15)) * PJ_LDS
                                          + ks * 16 + (lane >> 4) * 8) * 2;
                ldsm4(ah[mt], sAh + off);
                ldsm4(al[mt], sAl + off);
            }
            // split-pass ordering (accumulator re-hit gap 8)
            #pragma unroll
            for (int mt = 0; mt < 2; ++mt)
                #pragma unroll
                for (int nt = 0; nt < 4; ++nt)
                    mma_bf16(acc[mt][nt], ah[mt], bh[nt]);
            #pragma unroll
            for (int mt = 0; mt < 2; ++mt)
                #pragma unroll
                for (int nt = 0; nt < 4; ++nt)
                    mma_bf16(acc[mt][nt], ah[mt], bl[nt]);
            #pragma unroll
            for (int mt = 0; mt < 2; ++mt)
                #pragma unroll
                for (int nt = 0; nt < 4; ++nt)
                    mma_bf16(acc[mt][nt], al[mt], bh[nt]);
        }

        if (more) {
            int bufn = bufc + 1; if (bufn >= 3) bufn -= 3;
            uint32_t hiw[8], low[8];
            split16(xv, hiw, low);
            char* nbp = smem + (size_t)bufn * PJ_BUF_B;
            *(uint4*)(nbp + PJ_OF_AH + a_so)      = make_uint4(hiw[0], hiw[1], hiw[2], hiw[3]);
            *(uint4*)(nbp + PJ_OF_AH + a_so + 16) = make_uint4(hiw[4], hiw[5], hiw[6], hiw[7]);
            *(uint4*)(nbp + PJ_OF_AL + a_so)      = make_uint4(low[0], low[1], low[2], low[3]);
            *(uint4*)(nbp + PJ_OF_AL + a_so + 16) = make_uint4(low[4], low[5], low[6], low[7]);
        }
        if (++bufc >= 3) bufc = 0;
    }

    // epilogue: bias (+log2e scale for Q) + fp16 split/plain store
    const float* bias = (head == 0) ? bq : (head == 1) ? bk : bv;
    const float scl = (head == 0) ? LOG2E : 1.0f;
    const int qrow = lane >> 2;
    const int qcol = (lane & 3) * 2;
    #pragma unroll
    for (int mt = 0; mt < 2; ++mt) {
        int row0 = m0 + wm * 32 + mt * 16 + qrow;
        #pragma unroll
        for (int nt = 0; nt < 4; ++nt) {
            int col = wn * 32 + nt * 8 + qcol;
            float b0 = __ldg(bias + col), b1 = __ldg(bias + col + 1);
            float v0 = (acc[mt][nt][0] + b0) * scl;
            float v1 = (acc[mt][nt][1] + b1) * scl;
            float v2 = (acc[mt][nt][2] + b0) * scl;
            float v3 = (acc[mt][nt][3] + b1) * scl;
            size_t i0 = (size_t)row0 * HD + col;
            size_t i1 = (size_t)(row0 + 8) * HD + col;
            if (head == 0) {
                split_store(g_qh, g_ql, i0, v0, v1);
                split_store(g_qh, g_ql, i1, v2, v3);
            } else if (head == 1) {
                split_store(g_kh, g_kl, i0, v0, v1);
                split_store(g_kh, g_kl, i1, v2, v3);
            } else {
                *(uint32_t*)(g_vv + i0) = packh2(v0, v1);
                *(uint32_t*)(g_vv + i1) = packh2(v2, v3);
            }
        }
    }
}

// =====================================================================
// Kernel 2: fp16 tensor-core causal flash attention, SPLIT-KV.
// (round-13 champion version: batched frag loads, separate merge)
// =====================================================================
#define QSTRB 272
#define VSTRB 304
#define ST_B  54272
#define ST_KH 0
#define ST_KL 17408
#define ST_V  34816
#define SM_TASK 108544
#define SM_ATT_TOT 108560

__global__ __launch_bounds__(128)
void attn_kernel()
{
    extern __shared__ char smem[];
    const uint32_t sb = smem_u32(smem);
    const int t = threadIdx.x;
    const int l = t & 31;
    const int w = t >> 5;

    // init V pad columns for BOTH stages (col 128 = ones, 129..143 = 0)
    #pragma unroll
    for (int s2 = 0; s2 < 2; ++s2)
        for (int i = t; i < 64 * 16; i += 128) {
            int row = i >> 4;
            int c   = 128 + (i & 15);
            ((__half*)(smem + s2 * ST_B + ST_V))[row * 152 + c] =
                (c == 128) ? __float2half(1.0f) : __float2half(0.0f);
        }

    const uint32_t qa_off = (uint32_t)(w * 16 + (l & 15)) * QSTRB + ((l >> 4) * 8) * 2;
    const uint32_t kb_row = (uint32_t)((l >> 4) * 8 + (l & 7)) * QSTRB;
    const uint32_t kb_col = (uint32_t)(((l >> 3) & 1) * 8) * 2;
    const uint32_t vb_row = (uint32_t)(((l >> 3) & 1) * 8 + (l & 7)) * VSTRB;
    const uint32_t vb_col = (uint32_t)((l >> 4) * 8) * 2;

    while (true) {
        __syncthreads();
        if (t == 0) *(int*)(smem + SM_TASK) = atomicAdd(&g_task, 1);
        __syncthreads();
        const int task = *(int*)(smem + SM_TASK);
        if (task >= N_TASKS) break;

        int id = task, qb = 63, ch, b;
        for (;;) {
            int cnt = 4 * ((qb >> 3) + 1);
            if (id < cnt) { ch = id >> 2; b = id & 3; break; }
            id -= cnt; --qb;
        }
        const int q0  = qb * 64;
        const int kv0 = ch * CHUNK;
        const int kv1 = min(kv0 + CHUNK, qb + 1);

        const __half* qh = g_qh + (size_t)b * S_LEN * HD;
        const __half* ql = g_ql + (size_t)b * S_LEN * HD;
        const __half* kh = g_kh + (size_t)b * S_LEN * HD;
        const __half* kl = g_kl + (size_t)b * S_LEN * HD;
        const __half* vv = g_vv + (size_t)b * S_LEN * HD;

        #pragma unroll
        for (int p = 0; p < 8; ++p) {
            int vec = t + 128 * p;
            int row = vec >> 4;
            int cv  = vec & 15;
            uint32_t so = (uint32_t)row * QSTRB + cv * 16;
            const size_t g = (size_t)(q0 + row) * HD + cv * 8;
            cp16(sb + ST_KH + so, qh + g);
            cp16(sb + ST_KL + so, ql + g);
        }
        cp_commit();
        cp_wait0();
        __syncthreads();

        uint32_t qah[8][4], qal[8][4];
        #pragma unroll
        for (int ks = 0; ks < 8; ++ks) {
            ldsm4(qah[ks], sb + ST_KH + qa_off + ks * 32);
            ldsm4(qal[ks], sb + ST_KL + qa_off + ks * 32);
        }
        __syncthreads();

        #pragma unroll
        for (int p = 0; p < 8; ++p) {
            int vec = t + 128 * p;
            int row = vec >> 4;
            int cv  = vec & 15;
            const size_t g = (size_t)(kv0 * 64 + row) * HD + cv * 8;
            cp16(sb + (uint32_t)(kv0 & 1) * ST_B + ST_KH + (uint32_t)row * QSTRB + cv * 16, kh + g);
            cp16(sb + (uint32_t)(kv0 & 1) * ST_B + ST_KL + (uint32_t)row * QSTRB + cv * 16, kl + g);
            cp16(sb + (uint32_t)(kv0 & 1) * ST_B + ST_V  + (uint32_t)row * VSTRB + cv * 16, vv + g);
        }
        cp_commit();

        float o[18][4];
        #pragma unroll
        for (int i = 0; i < 18; ++i)
            #pragma unroll
            for (int u = 0; u < 4; ++u) o[i][u] = 0.f;
        float mA = -1e4f, mB = -1e4f;

        const int rA = w * 16 + (l >> 2);
        const int rB = rA + 8;

        for (int kb = kv0; kb < kv1; ++kb) {
            cp_wait0();
            __syncthreads();

            const uint32_t cb = sb + (uint32_t)(kb & 1) * ST_B;

            float s[8][4];
            #pragma unroll
            for (int n = 0; n < 8; ++n)
                #pragma unroll
                for (int u = 0; u < 4; ++u) s[n][u] = 0.f;

            #pragma unroll
            for (int ks = 0; ks < 8; ++ks) {
                uint32_t bh[4][4], bl[4][4];
                #pragma unroll
                for (int u = 0; u < 4; ++u) {
                    uint32_t off = (uint32_t)(u * 16) * QSTRB + kb_row + ks * 32 + kb_col;
                    ldsm4(bh[u], cb + ST_KH + off);
                    ldsm4(bl[u], cb + ST_KL + off);
                }
                #pragma unroll
                for (int u = 0; u < 4; ++u) {
                    mma_f16(s[2 * u],     qah[ks][0], qah[ks][1], qah[ks][2], qah[ks][3], bh[u][0], bh[u][1]);
                    mma_f16(s[2 * u + 1], qah[ks][0], qah[ks][1], qah[ks][2], qah[ks][3], bh[u][2], bh[u][3]);
                }
                #pragma unroll
                for (int u = 0; u < 4; ++u) {
                    mma_f16(s[2 * u],     qah[ks][0], qah[ks][1], qah[ks][2], qah[ks][3], bl[u][0], bl[u][1]);
                    mma_f16(s[2 * u + 1], qah[ks][0], qah[ks][1], qah[ks][2], qah[ks][3], bl[u][2], bl[u][3]);
                }
                #pragma unroll
                for (int u = 0; u < 4; ++u) {
                    mma_f16(s[2 * u],     qal[ks][0], qal[ks][1], qal[ks][2], qal[ks][3], bh[u][0], bh[u][1]);
                    mma_f16(s[2 * u + 1], qal[ks][0], qal[ks][1], qal[ks][2], qal[ks][3], bh[u][2], bh[u][3]);
                }
            }

            if (kb + 1 < kv1) {
                const uint32_t nb = sb + (uint32_t)((kb + 1) & 1) * ST_B;
                #pragma unroll
                for (int p = 0; p < 8; ++p) {
                    int vec = t + 128 * p;
                    int row = vec >> 4;
                    int cv  = vec & 15;
                    const size_t g = (size_t)((kb + 1) * 64 + row) * HD + cv * 8;
                    cp16(nb + ST_KH + (uint32_t)row * QSTRB + cv * 16, kh + g);
                    cp16(nb + ST_KL + (uint32_t)row * QSTRB + cv * 16, kl + g);
                    cp16(nb + ST_V  + (uint32_t)row * VSTRB + cv * 16, vv + g);
                }
                cp_commit();
            }

            if (kb == qb) {
                #pragma unroll
                for (int n = 0; n < 8; ++n) {
                    int c0 = n * 8 + 2 * (l & 3);
                    if (c0     > rA) s[n][0] = -1e30f;
                    if (c0 + 1 > rA) s[n][1] = -1e30f;
                    if (c0     > rB) s[n][2] = -1e30f;
                    if (c0 + 1 > rB) s[n][3] = -1e30f;
                }
            }

            float mxA = s[0][0], mxB = s[0][2];
            #pragma unroll
            for (int n = 0; n < 8; ++n) {
                mxA = fmaxf(mxA, fmaxf(s[n][0], s[n][1]));
                mxB = fmaxf(mxB, fmaxf(s[n][2], s[n][3]));
            }
            mxA = fmaxf(mxA, __shfl_xor_sync(0xffffffffu, mxA, 1));
            mxA = fmaxf(mxA, __shfl_xor_sync(0xffffffffu, mxA, 2));
            mxB = fmaxf(mxB, __shfl_xor_sync(0xffffffffu, mxB, 1));
            mxB = fmaxf(mxB, __shfl_xor_sync(0xffffffffu, mxB, 2));
            const float nmA = fmaxf(mA, mxA);
            const float nmB = fmaxf(mB, mxB);

            uint32_t pA[8], pB[8];
            #pragma unroll
            for (int n = 0; n < 8; ++n) {
                pA[n] = h2ex2(packh2(s[n][0] - nmA, s[n][1] - nmA));
                pB[n] = h2ex2(packh2(s[n][2] - nmB, s[n][3] - nmB));
            }

            if (nmA > mA) {
                float aA = ex2f(mA - nmA);
                #pragma unroll
                for (int i = 0; i < 17; ++i) { o[i][0] *= aA; o[i][1] *= aA; }
                mA = nmA;
            }
            if (nmB > mB) {
                float aB = ex2f(mB - nmB);
                #pragma unroll
                for (int i = 0; i < 17; ++i) { o[i][2] *= aB; o[i][3] *= aB; }
                mB = nmB;
            }

            #pragma unroll
            for (int kt = 0; kt < 4; ++kt) {
                uint32_t a0 = pA[2 * kt], a1 = pB[2 * kt];
                uint32_t a2 = pA[2 * kt + 1], a3 = pB[2 * kt + 1];
                uint32_t vb[9][4];
                #pragma unroll
                for (int u = 0; u < 9; ++u) {
                    uint32_t off = (uint32_t)(kt * 16) * VSTRB + vb_row + u * 32 + vb_col;
                    ldsm4t(vb[u], cb + ST_V + off);
                }
                #pragma unroll
                for (int u = 0; u < 9; ++u) {
                    mma_f16(o[2 * u],     a0, a1, a2, a3, vb[u][0], vb[u][1]);
                    mma_f16(o[2 * u + 1], a0, a1, a2, a3, vb[u][2], vb[u][3]);
                }
            }
            __syncthreads();
        }

        __half (*po)[HD] = g_po[task];
        #pragma unroll
        for (int n = 0; n < 16; ++n) {
            int c = n * 8 + 2 * (l & 3);
            *(uint32_t*)(&po[rA][c]) = packh2(o[n][0], o[n][1]);
            *(uint32_t*)(&po[rB][c]) = packh2(o[n][2], o[n][3]);
        }
        if ((l & 3) == 0) {
            g_pml[task][rA][0] = mA;
            g_pml[task][rA][1] = o[16][0];
            g_pml[task][rB][0] = mB;
            g_pml[task][rB][1] = o[16][2];
        }
    }
}

// =====================================================================
// Kernel 3: merge partials.  grid (64, 4, 4) = (qb, b, 16-row group);
// 1024 CTAs x 256 threads. (round-13 champion version)
// =====================================================================
__global__ void merge_kernel(float* __restrict__ outp)
{
    const int qb = blockIdx.x;
    const int b  = blockIdx.y;
    const int rg = blockIdx.z;
    const int nch = (qb >> 3) + 1;
    const int t = threadIdx.x;

    __shared__ float wsh[8][16];
    __shared__ float ssc[16];

    int base = 0;
    for (int q = 63; q > qb; --q) base += 4 * ((q >> 3) + 1);
    const int r0 = rg * 16;

    if (t < 16) {
        float m[8], lv[8];
        float M = -1e30f;
        for (int i = 0; i < nch; ++i) {
            int slot = base + 4 * i + b;
            m[i]  = g_pml[slot][r0 + t][0];
            lv[i] = g_pml[slot][r0 + t][1];
            M = fmaxf(M, m[i]);
        }
        float L = 0.f;
        for (int i = 0; i < nch; ++i) {
            float wi = ex2f(m[i] - M);
            wsh[i][t] = wi;
            L += wi * lv[i];
        }
        ssc[t] = 0.0883883476483184406f / L;
    }
    __syncthreads();

    float* op = outp + ((size_t)b * S_LEN + qb * 64 + r0) * HD;
    #pragma unroll
    for (int e = t; e < 16 * 64; e += 256) {
        int r  = e >> 6;
        int h2 = e & 63;
        float ax = 0.f, ay = 0.f;
        for (int i = 0; i < nch; ++i) {
            int slot = base + 4 * i + b;
            __half2 v = ((const __half2*)g_po[slot][r0 + r])[h2];
            float2 f = __half22float2(v);
            ax += wsh[i][r] * f.x;
            ay += wsh[i][r] * f.y;
        }
        float2 res;
        res.x = ax * ssc[r];
        res.y = ay * ssc[r];
        *(float2*)(op + (size_t)r * HD + 2 * h2) = res;
    }
}

// =====================================================================
extern "C" void kernel_launch(void* const* d_in, const int* in_sizes, int n_in,
                              void* d_out, int out_size)
{
    const float* x  = (const float*)d_in[0];
    const float* Wq = (const float*)d_in[1];
    const float* bq = (const float*)d_in[2];
    const float* Wk = (const float*)d_in[3];
    const float* bk = (const float*)d_in[4];
    const float* Wv = (const float*)d_in[5];
    const float* bv = (const float*)d_in[6];
    float* out = (float*)d_out;

    dim3 cwg(2, 32, 3);
    convert_w_kernel<<<cwg, 256>>>(Wq, Wk, Wv);

    cudaFuncSetAttribute(proj_mma_kernel,
                         cudaFuncAttributeMaxDynamicSharedMemorySize, PJ_SM_TOT);
    dim3 pg(3, 128);
    proj_mma_kernel<<<pg, 512, PJ_SM_TOT>>>(x, bq, bk, bv);

    cudaFuncSetAttribute(attn_kernel,
                         cudaFuncAttributeMaxDynamicSharedMemorySize, SM_ATT_TOT);
    attn_kernel<<<296, 128, SM_ATT_TOT>>>();

    dim3 mg(64, NB, 4);
    merge_kernel<<<mg, 256>>>(out);
}

// round 17
// speedup vs baseline: 1.0545x; 1.0179x over previous
#include <cuda_runtime.h>
#include <cuda_bf16.h>
#include <cuda_fp16.h>
#include <math.h>
#include <stdint.h>

#define NB    4
#define S_LEN 4096
#define HID   2048
#define HD    128
#define NROWS (NB * S_LEN)          // 16384
#define LOG2E 1.4426950408889634f

// Split-KV chunking: chunk = 16 KV blocks.  nch(qb) = (qb>>4)+1.
// total tasks = 4 * sum_{qb} nch = 4 * 160 = 640.
#define CHUNK    16
#define N_TASKS  640
#define MAXCH    4

// ---------------- scratch (no allocs allowed) ----------------
__device__ __nv_bfloat16 g_wthi[3 * HD * HID];   // [head][n][k] = W^T split hi
__device__ __nv_bfloat16 g_wtlo[3 * HD * HID];
__device__ __half g_qh[NROWS * HD];   // Q*log2e hi/lo fp16
__device__ __half g_ql[NROWS * HD];
__device__ __half g_kh[NROWS * HD];
__device__ __half g_kl[NROWS * HD];
__device__ __half g_vv[NROWS * HD];   // V fp16
__device__ __half g_po[N_TASKS][64][HD];  // unnormalized partial O (fp16)
__device__ float g_pml[N_TASKS][64][2];   // per-row {m, l}
__device__ int g_task;

// ======================= helpers =======================
__device__ __forceinline__ uint32_t smem_u32(const void* p) {
    uint32_t a;
    asm("{ .reg .u64 t; cvta.to.shared.u64 t, %1; cvt.u32.u64 %0, t; }" : "=r"(a) : "l"(p));
    return a;
}
__device__ __forceinline__ void cp16(uint32_t s, const void* g) {
    asm volatile("cp.async.cg.shared.global [%0], [%1], 16;" :: "r"(s), "l"(g));
}
__device__ __forceinline__ void cp_commit() {
    asm volatile("cp.async.commit_group;" ::: "memory");
}
__device__ __forceinline__ void cp_wait0() {
    asm volatile("cp.async.wait_group 0;" ::: "memory");
}
__device__ __forceinline__ void cp_wait1() {
    asm volatile("cp.async.wait_group 1;" ::: "memory");
}
__device__ __forceinline__ void cp_wait2() {
    asm volatile("cp.async.wait_group 2;" ::: "memory");
}
__device__ __forceinline__ void ldsm4(uint32_t* r, uint32_t addr) {
    asm volatile("ldmatrix.sync.aligned.m8n8.x4.shared.b16 {%0,%1,%2,%3}, [%4];"
                 : "=r"(r[0]), "=r"(r[1]), "=r"(r[2]), "=r"(r[3]) : "r"(addr));
}
__device__ __forceinline__ void ldsm4t(uint32_t* r, uint32_t addr) {
    asm volatile("ldmatrix.sync.aligned.m8n8.x4.trans.shared.b16 {%0,%1,%2,%3}, [%4];"
                 : "=r"(r[0]), "=r"(r[1]), "=r"(r[2]), "=r"(r[3]) : "r"(addr));
}
__device__ __forceinline__ void mma_bf16(float* d, const uint32_t* a, const uint32_t* b) {
    asm volatile(
        "mma.sync.aligned.m16n8k16.row.col.f32.bf16.bf16.f32 "
        "{%0,%1,%2,%3}, {%4,%5,%6,%7}, {%8,%9}, {%0,%1,%2,%3};"
        : "+f"(d[0]), "+f"(d[1]), "+f"(d[2]), "+f"(d[3])
        : "r"(a[0]), "r"(a[1]), "r"(a[2]), "r"(a[3]), "r"(b[0]), "r"(b[1]));
}
__device__ __forceinline__ void mma_f16(float* d, uint32_t a0, uint32_t a1, uint32_t a2,
                                        uint32_t a3, uint32_t b0, uint32_t b1) {
    asm volatile(
        "mma.sync.aligned.m16n8k16.row.col.f32.f16.f16.f32 "
        "{%0,%1,%2,%3}, {%4,%5,%6,%7}, {%8,%9}, {%0,%1,%2,%3};"
        : "+f"(d[0]), "+f"(d[1]), "+f"(d[2]), "+f"(d[3])
        : "r"(a0), "r"(a1), "r"(a2), "r"(a3), "r"(b0), "r"(b1));
}
__device__ __forceinline__ float ex2f(float x) {
    float r;
    asm("ex2.approx.f32 %0, %1;" : "=f"(r) : "f"(x));
    return r;
}
__device__ __forceinline__ uint32_t packh2(float lo, float hi) {
    uint32_t r;
    asm("cvt.rn.f16x2.f32 %0, %1, %2;" : "=r"(r) : "f"(hi), "f"(lo));
    return r;
}
__device__ __forceinline__ uint32_t h2ex2(uint32_t x) {
    uint32_t r;
    asm("ex2.approx.f16x2 %0, %1;" : "=r"(r) : "r"(x));
    return r;
}

// =====================================================================
// Kernel 0: transpose+split W via smem tiles (coalesced both sides).
// grid (2, 32, 3) = (n-tile, k-tile, head); 256 threads; 64x64 tiles.
// Also resets the persistent-attention task counter.
// =====================================================================
__global__ void convert_w_kernel(const float* __restrict__ Wq,
                                 const float* __restrict__ Wk,
                                 const float* __restrict__ Wv)
{
    __shared__ float ts[64][65];
    const int t = threadIdx.x;
    if (blockIdx.x == 0 && blockIdx.y == 0 && blockIdx.z == 0 && t == 0) g_task = 0;

    const int head = blockIdx.z;
    const int k0 = blockIdx.y * 64;
    const int n0 = blockIdx.x * 64;
    const float* W = (head == 0) ? Wq : (head == 1) ? Wk : Wv;

    // coalesced load: 64x64 fp32 tile
    {
        const int r = t >> 4;            // 0..15
        const int c = (t & 15) * 4;      // 0..60
        #pragma unroll
        for (int i = 0; i < 4; ++i) {
            float4 v = *(const float4*)(W + (size_t)(k0 + r + i * 16) * HD + n0 + c);
            ts[r + i * 16][c]     = v.x;
            ts[r + i * 16][c + 1] = v.y;
            ts[r + i * 16][c + 2] = v.z;
            ts[r + i * 16][c + 3] = v.w;
        }
    }
    __syncthreads();

    // transposed, split, coalesced store: each thread owns (n, 16 k's)
    {
        const int n   = t >> 2;          // 0..63
        const int ks0 = (t & 3) * 16;    // 0,16,32,48
        uint32_t hw[8], lw[8];
        #pragma unroll
        for (int j = 0; j < 8; ++j) {
            float v0 = ts[ks0 + 2 * j][n];
            float v1 = ts[ks0 + 2 * j + 1][n];
            __nv_bfloat16 h0 = __float2bfloat16(v0);
            __nv_bfloat16 h1 = __float2bfloat16(v1);
            __nv_bfloat16 l0 = __float2bfloat16(v0 - __bfloat162float(h0));
            __nv_bfloat16 l1 = __float2bfloat16(v1 - __bfloat162float(h1));
            __nv_bfloat162 hp = __halves2bfloat162(h0, h1);
            __nv_bfloat162 lp = __halves2bfloat162(l0, l1);
            hw[j] = *(uint32_t*)&hp;
            lw[j] = *(uint32_t*)&lp;
        }
        size_t base = (size_t)head * HD * HID + (size_t)(n0 + n) * HID + k0 + ks0;
        *(uint4*)(g_wthi + base)     = make_uint4(hw[0], hw[1], hw[2], hw[3]);
        *(uint4*)(g_wthi + base + 8) = make_uint4(hw[4], hw[5], hw[6], hw[7]);
        *(uint4*)(g_wtlo + base)     = make_uint4(lw[0], lw[1], lw[2], lw[3]);
        *(uint4*)(g_wtlo + base + 8) = make_uint4(lw[4], lw[5], lw[6], lw[7]);
    }
}

// =====================================================================
// Kernel 1: mma.sync bf16-split projection with FUSED x split.
// 512 threads (16 warps, 4x4, 32x32 warp tiles), 1 CTA/SM, grid(3,128).
// BK=64, 3-stage cp.async pipeline (round-13 champion version).
// =====================================================================
#define PJ_BK     64
#define PJ_NCHUNK (HID / PJ_BK)        // 32
#define PJ_LDS    72
#define PJ_TILE_B (128 * PJ_LDS * 2)
#define PJ_OF_AH  0
#define PJ_OF_AL  (PJ_TILE_B)
#define PJ_OF_BH  (2 * PJ_TILE_B)
#define PJ_OF_BL  (3 * PJ_TILE_B)
#define PJ_BUF_B  (4 * PJ_TILE_B)
#define PJ_SM_TOT (3 * PJ_BUF_B)        // 221184

__device__ __forceinline__ void split_store(__half* hi, __half* lo, size_t idx,
                                            float v0, float v1) {
    __half h0 = __float2half_rn(v0), h1 = __float2half_rn(v1);
    __half l0 = __float2half_rn(v0 - __half2float(h0));
    __half l1 = __float2half_rn(v1 - __half2float(h1));
    *(__half2*)(hi + idx) = __halves2half2(h0, h1);
    *(__half2*)(lo + idx) = __halves2half2(l0, l1);
}

// convert 16 fp32 (4 float4) -> 8+8 packed bf16x2 words (hi, lo)
__device__ __forceinline__ void split16(const float4* xv, uint32_t* hiw, uint32_t* low) {
    #pragma unroll
    for (int j = 0; j < 4; ++j) {
        float e[4] = {xv[j].x, xv[j].y, xv[j].z, xv[j].w};
        __nv_bfloat16 h[4], l[4];
        #pragma unroll
        for (int u = 0; u < 4; ++u) {
            h[u] = __float2bfloat16(e[u]);
            l[u] = __float2bfloat16(e[u] - __bfloat162float(h[u]));
        }
        __nv_bfloat162 hp0 = __halves2bfloat162(h[0], h[1]);
        __nv_bfloat162 hp1 = __halves2bfloat162(h[2], h[3]);
        __nv_bfloat162 lp0 = __halves2bfloat162(l[0], l[1]);
        __nv_bfloat162 lp1 = __halves2bfloat162(l[2], l[3]);
        hiw[2 * j]     = *(uint32_t*)&hp0;
        hiw[2 * j + 1] = *(uint32_t*)&hp1;
        low[2 * j]     = *(uint32_t*)&lp0;
        low[2 * j + 1] = *(uint32_t*)&lp1;
    }
}

__global__ __launch_bounds__(512, 1)
void proj_mma_kernel(const float* __restrict__ x,
                     const float* __restrict__ bq,
                     const float* __restrict__ bk,
                     const float* __restrict__ bv)
{
    extern __shared__ char smem[];
    const uint32_t sb = smem_u32(smem);

    const int t    = threadIdx.x;
    const int lane = t & 31;
    const int wid  = t >> 5;
    const int wm   = wid >> 2;
    const int wn   = wid & 3;
    const int head = blockIdx.x;
    const int m0   = blockIdx.y * 128;

    const __nv_bfloat16* wh = g_wthi + (size_t)head * HD * HID;
    const __nv_bfloat16* wl = g_wtlo + (size_t)head * HD * HID;

    const int lrow = t >> 2;
    const int lcs  = (t & 3) * 16;
    const float* xrow = x + (size_t)(m0 + lrow) * HID + lcs;
    const uint32_t a_so = (uint32_t)(lrow * PJ_LDS + lcs) * 2;
    const uint32_t b_so = (uint32_t)(lrow * PJ_LDS + lcs) * 2;
    const __nv_bfloat16* whrow = wh + (size_t)lrow * HID + lcs;
    const __nv_bfloat16* wlrow = wl + (size_t)lrow * HID + lcs;

    float acc[2][4][4];
    #pragma unroll
    for (int i = 0; i < 2; ++i)
        #pragma unroll
        for (int j = 0; j < 4; ++j)
            #pragma unroll
            for (int u = 0; u < 4; ++u) acc[i][j][u] = 0.f;

    {
        cp16(sb + PJ_OF_BH + b_so,      whrow);
        cp16(sb + PJ_OF_BH + b_so + 16, whrow + 8);
        cp16(sb + PJ_OF_BL + b_so,      wlrow);
        cp16(sb + PJ_OF_BL + b_so + 16, wlrow + 8);
        cp_commit();
        const uint32_t b1 = sb + PJ_BUF_B;
        cp16(b1 + PJ_OF_BH + b_so,      whrow + PJ_BK);
        cp16(b1 + PJ_OF_BH + b_so + 16, whrow + PJ_BK + 8);
        cp16(b1 + PJ_OF_BL + b_so,      wlrow + PJ_BK);
        cp16(b1 + PJ_OF_BL + b_so + 16, wlrow + PJ_BK + 8);
        cp_commit();
        float4 xv[4];
        #pragma unroll
        for (int j = 0; j < 4; ++j) xv[j] = ((const float4*)xrow)[j];
        uint32_t hiw[8], low[8];
        split16(xv, hiw, low);
        *(uint4*)(smem + PJ_OF_AH + a_so)      = make_uint4(hiw[0], hiw[1], hiw[2], hiw[3]);
        *(uint4*)(smem + PJ_OF_AH + a_so + 16) = make_uint4(hiw[4], hiw[5], hiw[6], hiw[7]);
        *(uint4*)(smem + PJ_OF_AL + a_so)      = make_uint4(low[0], low[1], low[2], low[3]);
        *(uint4*)(smem + PJ_OF_AL + a_so + 16) = make_uint4(low[4], low[5], low[6], low[7]);
    }

    int bufc = 0;
    for (int c = 0; c < PJ_NCHUNK; ++c) {
        if (c + 2 < PJ_NCHUNK) {
            const int kt = (c + 2) * PJ_BK;
            int bufn2 = bufc + 2; if (bufn2 >= 3) bufn2 -= 3;
            const uint32_t nb = sb + (uint32_t)bufn2 * PJ_BUF_B;
            cp16(nb + PJ_OF_BH + b_so,      whrow + kt);
            cp16(nb + PJ_OF_BH + b_so + 16, whrow + kt + 8);
            cp16(nb + PJ_OF_BL + b_so,      wlrow + kt);
            cp16(nb + PJ_OF_BL + b_so + 16, wlrow + kt + 8);
            cp_commit();
            cp_wait2();
        } else if (c + 1 < PJ_NCHUNK) {
            cp_wait1();
        } else {
            cp_wait0();
        }
        __syncthreads();

        float4 xv[4];
        const bool more = (c + 1 < PJ_NCHUNK);
        if (more) {
            const int kt = (c + 1) * PJ_BK;
            #pragma unroll
            for (int j = 0; j < 4; ++j) xv[j] = ((const float4*)(xrow + kt))[j];
        }

        const uint32_t bbase = sb + (uint32_t)bufc * PJ_BUF_B;
        const uint32_t sAh = bbase + PJ_OF_AH;
        const uint32_t sAl = bbase + PJ_OF_AL;
        const uint32_t sBh = bbase + PJ_OF_BH;
        const uint32_t sBl = bbase + PJ_OF_BL;

        #pragma unroll
        for (int ks = 0; ks < 4; ++ks) {
            uint32_t bh[4][2], bl[4][2];
            #pragma unroll
            for (int g = 0; g < 2; ++g) {
                uint32_t off = (uint32_t)((wn * 32 + g * 16 + (lane & 15)) * PJ_LDS
                                          + ks * 16 + (lane >> 4) * 8) * 2;
                uint32_t r[4];
                ldsm4(r, sBh + off);
                bh[2 * g][0] = r[0]; bh[2 * g + 1][0] = r[1];
                bh[2 * g][1] = r[2]; bh[2 * g + 1][1] = r[3];
                ldsm4(r, sBl + off);
                bl[2 * g][0] = r[0]; bl[2 * g + 1][0] = r[1];
                bl[2 * g][1] = r[2]; bl[2 * g + 1][1] = r[3];
            }
            uint32_t ah[2][4], al[2][4];
            #pragma unroll
            for (int mt = 0; mt < 2; ++mt) {
                uint32_t off = (uint32_t)((wm * 32 + mt * 16 + (lane & 15)) * PJ_LDS
                                          + ks * 16 + (lane >> 4) * 8) * 2;
                ldsm4(ah[mt], sAh + off);
                ldsm4(al[mt], sAl + off);
            }
            // split-pass ordering (accumulator re-hit gap 8)
            #pragma unroll
            for (int mt = 0; mt < 2; ++mt)
                #pragma unroll
                for (int nt = 0; nt < 4; ++nt)
                    mma_bf16(acc[mt][nt], ah[mt], bh[nt]);
            #pragma unroll
            for (int mt = 0; mt < 2; ++mt)
                #pragma unroll
                for (int nt = 0; nt < 4; ++nt)
                    mma_bf16(acc[mt][nt], ah[mt], bl[nt]);
            #pragma unroll
            for (int mt = 0; mt < 2; ++mt)
                #pragma unroll
                for (int nt = 0; nt < 4; ++nt)
                    mma_bf16(acc[mt][nt], al[mt], bh[nt]);
        }

        if (more) {
            int bufn = bufc + 1; if (bufn >= 3) bufn -= 3;
            uint32_t hiw[8], low[8];
            split16(xv, hiw, low);
            char* nbp = smem + (size_t)bufn * PJ_BUF_B;
            *(uint4*)(nbp + PJ_OF_AH + a_so)      = make_uint4(hiw[0], hiw[1], hiw[2], hiw[3]);
            *(uint4*)(nbp + PJ_OF_AH + a_so + 16) = make_uint4(hiw[4], hiw[5], hiw[6], hiw[7]);
            *(uint4*)(nbp + PJ_OF_AL + a_so)      = make_uint4(low[0], low[1], low[2], low[3]);
            *(uint4*)(nbp + PJ_OF_AL + a_so + 16) = make_uint4(low[4], low[5], low[6], low[7]);
        }
        if (++bufc >= 3) bufc = 0;
    }

    // epilogue: bias (+log2e scale for Q) + fp16 split/plain store
    const float* bias = (head == 0) ? bq : (head == 1) ? bk : bv;
    const float scl = (head == 0) ? LOG2E : 1.0f;
    const int qrow = lane >> 2;
    const int qcol = (lane & 3) * 2;
    #pragma unroll
    for (int mt = 0; mt < 2; ++mt) {
        int row0 = m0 + wm * 32 + mt * 16 + qrow;
        #pragma unroll
        for (int nt = 0; nt < 4; ++nt) {
            int col = wn * 32 + nt * 8 + qcol;
            float b0 = __ldg(bias + col), b1 = __ldg(bias + col + 1);
            float v0 = (acc[mt][nt][0] + b0) * scl;
            float v1 = (acc[mt][nt][1] + b1) * scl;
            float v2 = (acc[mt][nt][2] + b0) * scl;
            float v3 = (acc[mt][nt][3] + b1) * scl;
            size_t i0 = (size_t)row0 * HD + col;
            size_t i1 = (size_t)(row0 + 8) * HD + col;
            if (head == 0) {
                split_store(g_qh, g_ql, i0, v0, v1);
                split_store(g_qh, g_ql, i1, v2, v3);
            } else if (head == 1) {
                split_store(g_kh, g_kl, i0, v0, v1);
                split_store(g_kh, g_kl, i1, v2, v3);
            } else {
                *(uint32_t*)(g_vv + i0) = packh2(v0, v1);
                *(uint32_t*)(g_vv + i1) = packh2(v2, v3);
            }
        }
    }
}

// =====================================================================
// Kernel 2: fp16 tensor-core causal flash attention, SPLIT-KV.
// (round-13 structure; CHUNK=16 -> 640 tasks, ~half per-task overhead)
// =====================================================================
#define QSTRB 272
#define VSTRB 304
#define ST_B  54272
#define ST_KH 0
#define ST_KL 17408
#define ST_V  34816
#define SM_TASK 108544
#define SM_ATT_TOT 108560

__global__ __launch_bounds__(128)
void attn_kernel()
{
    extern __shared__ char smem[];
    const uint32_t sb = smem_u32(smem);
    const int t = threadIdx.x;
    const int l = t & 31;
    const int w = t >> 5;

    // init V pad columns for BOTH stages (col 128 = ones, 129..143 = 0)
    #pragma unroll
    for (int s2 = 0; s2 < 2; ++s2)
        for (int i = t; i < 64 * 16; i += 128) {
            int row = i >> 4;
            int c   = 128 + (i & 15);
            ((__half*)(smem + s2 * ST_B + ST_V))[row * 152 + c] =
                (c == 128) ? __float2half(1.0f) : __float2half(0.0f);
        }

    const uint32_t qa_off = (uint32_t)(w * 16 + (l & 15)) * QSTRB + ((l >> 4) * 8) * 2;
    const uint32_t kb_row = (uint32_t)((l >> 4) * 8 + (l & 7)) * QSTRB;
    const uint32_t kb_col = (uint32_t)(((l >> 3) & 1) * 8) * 2;
    const uint32_t vb_row = (uint32_t)(((l >> 3) & 1) * 8 + (l & 7)) * VSTRB;
    const uint32_t vb_col = (uint32_t)((l >> 4) * 8) * 2;

    while (true) {
        __syncthreads();
        if (t == 0) *(int*)(smem + SM_TASK) = atomicAdd(&g_task, 1);
        __syncthreads();
        const int task = *(int*)(smem + SM_TASK);
        if (task >= N_TASKS) break;

        // decode task -> (qb desc, chunk, batch)
        int id = task, qb = 63, ch, b;
        for (;;) {
            int cnt = 4 * ((qb >> 4) + 1);
            if (id < cnt) { ch = id >> 2; b = id & 3; break; }
            id -= cnt; --qb;
        }
        const int q0  = qb * 64;
        const int kv0 = ch * CHUNK;
        const int kv1 = min(kv0 + CHUNK, qb + 1);

        const __half* qh = g_qh + (size_t)b * S_LEN * HD;
        const __half* ql = g_ql + (size_t)b * S_LEN * HD;
        const __half* kh = g_kh + (size_t)b * S_LEN * HD;
        const __half* kl = g_kl + (size_t)b * S_LEN * HD;
        const __half* vv = g_vv + (size_t)b * S_LEN * HD;

        #pragma unroll
        for (int p = 0; p < 8; ++p) {
            int vec = t + 128 * p;
            int row = vec >> 4;
            int cv  = vec & 15;
            uint32_t so = (uint32_t)row * QSTRB + cv * 16;
            const size_t g = (size_t)(q0 + row) * HD + cv * 8;
            cp16(sb + ST_KH + so, qh + g);
            cp16(sb + ST_KL + so, ql + g);
        }
        cp_commit();
        cp_wait0();
        __syncthreads();

        uint32_t qah[8][4], qal[8][4];
        #pragma unroll
        for (int ks = 0; ks < 8; ++ks) {
            ldsm4(qah[ks], sb + ST_KH + qa_off + ks * 32);
            ldsm4(qal[ks], sb + ST_KL + qa_off + ks * 32);
        }
        __syncthreads();

        #pragma unroll
        for (int p = 0; p < 8; ++p) {
            int vec = t + 128 * p;
            int row = vec >> 4;
            int cv  = vec & 15;
            const size_t g = (size_t)(kv0 * 64 + row) * HD + cv * 8;
            cp16(sb + (uint32_t)(kv0 & 1) * ST_B + ST_KH + (uint32_t)row * QSTRB + cv * 16, kh + g);
            cp16(sb + (uint32_t)(kv0 & 1) * ST_B + ST_KL + (uint32_t)row * QSTRB + cv * 16, kl + g);
            cp16(sb + (uint32_t)(kv0 & 1) * ST_B + ST_V  + (uint32_t)row * VSTRB + cv * 16, vv + g);
        }
        cp_commit();

        float o[18][4];
        #pragma unroll
        for (int i = 0; i < 18; ++i)
            #pragma unroll
            for (int u = 0; u < 4; ++u) o[i][u] = 0.f;
        float mA = -1e4f, mB = -1e4f;

        const int rA = w * 16 + (l >> 2);
        const int rB = rA + 8;

        for (int kb = kv0; kb < kv1; ++kb) {
            cp_wait0();
            __syncthreads();

            const uint32_t cb = sb + (uint32_t)(kb & 1) * ST_B;

            float s[8][4];
            #pragma unroll
            for (int n = 0; n < 8; ++n)
                #pragma unroll
                for (int u = 0; u < 4; ++u) s[n][u] = 0.f;

            #pragma unroll
            for (int ks = 0; ks < 8; ++ks) {
                uint32_t bh[4][4], bl[4][4];
                #pragma unroll
                for (int u = 0; u < 4; ++u) {
                    uint32_t off = (uint32_t)(u * 16) * QSTRB + kb_row + ks * 32 + kb_col;
                    ldsm4(bh[u], cb + ST_KH + off);
                    ldsm4(bl[u], cb + ST_KL + off);
                }
                #pragma unroll
                for (int u = 0; u < 4; ++u) {
                    mma_f16(s[2 * u],     qah[ks][0], qah[ks][1], qah[ks][2], qah[ks][3], bh[u][0], bh[u][1]);
                    mma_f16(s[2 * u + 1], qah[ks][0], qah[ks][1], qah[ks][2], qah[ks][3], bh[u][2], bh[u][3]);
                }
                #pragma unroll
                for (int u = 0; u < 4; ++u) {
                    mma_f16(s[2 * u],     qah[ks][0], qah[ks][1], qah[ks][2], qah[ks][3], bl[u][0], bl[u][1]);
                    mma_f16(s[2 * u + 1], qah[ks][0], qah[ks][1], qah[ks][2], qah[ks][3], bl[u][2], bl[u][3]);
                }
                #pragma unroll
                for (int u = 0; u < 4; ++u) {
                    mma_f16(s[2 * u],     qal[ks][0], qal[ks][1], qal[ks][2], qal[ks][3], bh[u][0], bh[u][1]);
                    mma_f16(s[2 * u + 1], qal[ks][0], qal[ks][1], qal[ks][2], qal[ks][3], bh[u][2], bh[u][3]);
                }
            }

            if (kb + 1 < kv1) {
                const uint32_t nb = sb + (uint32_t)((kb + 1) & 1) * ST_B;
                #pragma unroll
                for (int p = 0; p < 8; ++p) {
                    int vec = t + 128 * p;
                    int row = vec >> 4;
                    int cv  = vec & 15;
                    const size_t g = (size_t)((kb + 1) * 64 + row) * HD + cv * 8;
                    cp16(nb + ST_KH + (uint32_t)row * QSTRB + cv * 16, kh + g);
                    cp16(nb + ST_KL + (uint32_t)row * QSTRB + cv * 16, kl + g);
                    cp16(nb + ST_V  + (uint32_t)row * VSTRB + cv * 16, vv + g);
                }
                cp_commit();
            }

            if (kb == qb) {
                #pragma unroll
                for (int n = 0; n < 8; ++n) {
                    int c0 = n * 8 + 2 * (l & 3);
                    if (c0     > rA) s[n][0] = -1e30f;
                    if (c0 + 1 > rA) s[n][1] = -1e30f;
                    if (c0     > rB) s[n][2] = -1e30f;
                    if (c0 + 1 > rB) s[n][3] = -1e30f;
                }
            }

            float mxA = s[0][0], mxB = s[0][2];
            #pragma unroll
            for (int n = 0; n < 8; ++n) {
                mxA = fmaxf(mxA, fmaxf(s[n][0], s[n][1]));
                mxB = fmaxf(mxB, fmaxf(s[n][2], s[n][3]));
            }
            mxA = fmaxf(mxA, __shfl_xor_sync(0xffffffffu, mxA, 1));
            mxA = fmaxf(mxA, __shfl_xor_sync(0xffffffffu, mxA, 2));
            mxB = fmaxf(mxB, __shfl_xor_sync(0xffffffffu, mxB, 1));
            mxB = fmaxf(mxB, __shfl_xor_sync(0xffffffffu, mxB, 2));
            const float nmA = fmaxf(mA, mxA);
            const float nmB = fmaxf(mB, mxB);

            uint32_t pA[8], pB[8];
            #pragma unroll
            for (int n = 0; n < 8; ++n) {
                pA[n] = h2ex2(packh2(s[n][0] - nmA, s[n][1] - nmA));
                pB[n] = h2ex2(packh2(s[n][2] - nmB, s[n][3] - nmB));
            }

            if (nmA > mA) {
                float aA = ex2f(mA - nmA);
                #pragma unroll
                for (int i = 0; i < 17; ++i) { o[i][0] *= aA; o[i][1] *= aA; }
                mA = nmA;
            }
            if (nmB > mB) {
                float aB = ex2f(mB - nmB);
                #pragma unroll
                for (int i = 0; i < 17; ++i) { o[i][2] *= aB; o[i][3] *= aB; }
                mB = nmB;
            }

            #pragma unroll
            for (int kt = 0; kt < 4; ++kt) {
                uint32_t a0 = pA[2 * kt], a1 = pB[2 * kt];
                uint32_t a2 = pA[2 * kt + 1], a3 = pB[2 * kt + 1];
                uint32_t vb[9][4];
                #pragma unroll
                for (int u = 0; u < 9; ++u) {
                    uint32_t off = (uint32_t)(kt * 16) * VSTRB + vb_row + u * 32 + vb_col;
                    ldsm4t(vb[u], cb + ST_V + off);
                }
                #pragma unroll
                for (int u = 0; u < 9; ++u) {
                    mma_f16(o[2 * u],     a0, a1, a2, a3, vb[u][0], vb[u][1]);
                    mma_f16(o[2 * u + 1], a0, a1, a2, a3, vb[u][2], vb[u][3]);
                }
            }
            __syncthreads();
        }

        __half (*po)[HD] = g_po[task];
        #pragma unroll
        for (int n = 0; n < 16; ++n) {
            int c = n * 8 + 2 * (l & 3);
            *(uint32_t*)(&po[rA][c]) = packh2(o[n][0], o[n][1]);
            *(uint32_t*)(&po[rB][c]) = packh2(o[n][2], o[n][3]);
        }
        if ((l & 3) == 0) {
            g_pml[task][rA][0] = mA;
            g_pml[task][rA][1] = o[16][0];
            g_pml[task][rB][0] = mB;
            g_pml[task][rB][1] = o[16][2];
        }
    }
}

// =====================================================================
// Kernel 3: merge partials.  grid (64, 4, 4) = (qb, b, 16-row group);
// 1024 CTAs x 256 threads.  nch <= 4 with CHUNK=16.
// =====================================================================
__global__ void merge_kernel(float* __restrict__ outp)
{
    const int qb = blockIdx.x;
    const int b  = blockIdx.y;
    const int rg = blockIdx.z;
    const int nch = (qb >> 4) + 1;
    const int t = threadIdx.x;

    __shared__ float wsh[MAXCH][16];
    __shared__ float ssc[16];

    int base = 0;
    for (int q = 63; q > qb; --q) base += 4 * ((q >> 4) + 1);
    const int r0 = rg * 16;

    if (t < 16) {
        float m[MAXCH], lv[MAXCH];
        float M = -1e30f;
        for (int i = 0; i < nch; ++i) {
            int slot = base + 4 * i + b;
            m[i]  = g_pml[slot][r0 + t][0];
            lv[i] = g_pml[slot][r0 + t][1];
            M = fmaxf(M, m[i]);
        }
        float L = 0.f;
        for (int i = 0; i < nch; ++i) {
            float wi = ex2f(m[i] - M);
            wsh[i][t] = wi;
            L += wi * lv[i];
        }
        ssc[t] = 0.0883883476483184406f / L;
    }
    __syncthreads();

    float* op = outp + ((size_t)b * S_LEN + qb * 64 + r0) * HD;
    #pragma unroll
    for (int e = t; e < 16 * 64; e += 256) {
        int r  = e >> 6;
        int h2 = e & 63;
        float ax = 0.f, ay = 0.f;
        for (int i = 0; i < nch; ++i) {
            int slot = base + 4 * i + b;
            __half2 v = ((const __half2*)g_po[slot][r0 + r])[h2];
            float2 f = __half22float2(v);
            ax += wsh[i][r] * f.x;
            ay += wsh[i][r] * f.y;
        }
        float2 res;
        res.x = ax * ssc[r];
        res.y = ay * ssc[r];
        *(float2*)(op + (size_t)r * HD + 2 * h2) = res;
    }
}

// =====================================================================
extern "C" void kernel_launch(void* const* d_in, const int* in_sizes, int n_in,
                              void* d_out, int out_size)
{
    const float* x  = (const float*)d_in[0];
    const float* Wq = (const float*)d_in[1];
    const float* bq = (const float*)d_in[2];
    const float* Wk = (const float*)d_in[3];
    const float* bk = (const float*)d_in[4];
    const float* Wv = (const float*)d_in[5];
    const float* bv = (const float*)d_in[6];
    float* out = (float*)d_out;

    dim3 cwg(2, 32, 3);
    convert_w_kernel<<<cwg, 256>>>(Wq, Wk, Wv);

    cudaFuncSetAttribute(proj_mma_kernel,
                         cudaFuncAttributeMaxDynamicSharedMemorySize, PJ_SM_TOT);
    dim3 pg(3, 128);
    proj_mma_kernel<<<pg, 512, PJ_SM_TOT>>>(x, bq, bk, bv);

    cudaFuncSetAttribute(attn_kernel,
                         cudaFuncAttributeMaxDynamicSharedMemorySize, SM_ATT_TOT);
    attn_kernel<<<296, 128, SM_ATT_TOT>>>();

    dim3 mg(64, NB, 4);
    merge_kernel<<<mg, 256>>>(out);
}